// round 17
// baseline (speedup 1.0000x reference)
#include <cuda_runtime.h>

// x: (32, 256, 256, 16) float32, contiguous.
// p[h][w] = mean over b (32) and c (16) of x[b][h][w][c]   (512-way reduction)
// out = (p >= ALPHA) ? (ALPHA/p)*x : beta*x + (1-beta),  beta = (1-ALPHA)/(1-p)
// Both branches affine in x: out = a*x + c, per-(h,w) constants.
//
// Occupancy-tuned version of the fastest (R3) geometry:
//   4096 blocks x 256 threads, one block owns (h, w-16th): 16 w x 16 c x 32 b.
//   Thread t: pos4 = t & 63 (float4 slot in the 64-f4 contiguous per-batch
//   slice, w_local = pos4>>2), bgrp = t >> 6 (batches bgrp*8 .. +7).
//   8 float4 held in registers across the reduction (no DRAM re-read).
// Changes vs R3:
//   - ALL indexing in 32-bit (tensor is 2^23 float4; fits easily) -> fewer regs
//   - __launch_bounds__(256, 6): force <=42 regs -> 6 CTAs/SM (48 warps) for
//     deeper MLP; DRAM latency hiding is the measured limiter (occ ~ DRAM%).
//   - single barrier: partials -> smem -> sync -> every thread folds the 4
//     partials for its own w (3 adds + 1 div, redundant but barrier-free).

#define ALPHA_F 0.25f

static constexpr int BSTRIDE4 = 256 * 256 * 16 / 4;  // batch stride in float4 = 262144

__global__ void __launch_bounds__(256, 6)
rescale_prob_mask_kernel(const float* __restrict__ x, float* __restrict__ out) {
    __shared__ float s_part[4][16];   // [batch-group][w_local]

    const int t    = threadIdx.x;
    const int pos4 = t & 63;          // float4 slot within the per-batch slice
    const int bgrp = t >> 6;          // 0..3 -> 8 batches each
    const int w    = pos4 >> 2;       // 0..15 local w

    // block -> (h, w-chunk); all 32-bit
    const int h  = blockIdx.x >> 4;   // 0..255
    const int wq = blockIdx.x & 15;   // 0..15

    // float4 offset of this thread's first element (fits in 23 bits + batches)
    const int idx0 = h * 1024 + wq * 64 + pos4 + (bgrp * 8) * BSTRIDE4;

    const float4* __restrict__ x4 = (const float4*)x;
    float4*       __restrict__ o4 = (float4*)out;

    // ---- Load 8 float4 into registers (8 independent LDG.128, high MLP) ----
    float4 v[8];
#pragma unroll
    for (int j = 0; j < 8; j++)
        v[j] = x4[idx0 + j * BSTRIDE4];

    // ---- Reduce: each thread sums its 32 values ----
    float s = 0.0f;
#pragma unroll
    for (int j = 0; j < 8; j++)
        s += (v[j].x + v[j].y) + (v[j].z + v[j].w);

    // combine the 4 channel lanes sharing one w (lanes 4k..4k+3)
    s += __shfl_xor_sync(0xffffffffu, s, 1);
    s += __shfl_xor_sync(0xffffffffu, s, 2);

    if ((t & 3) == 0)
        s_part[bgrp][w] = s;          // per (batch-group, w) partial: 16c x 8b
    __syncthreads();                  // the ONLY barrier

    // every thread folds the 4 batch-group partials for its own w
    const float p = (s_part[0][w] + s_part[1][w] + s_part[2][w] + s_part[3][w])
                    * (1.0f / 512.0f);
    float a, c;
    if (p >= ALPHA_F) {
        a = ALPHA_F / p;
        c = 0.0f;
    } else {
        const float beta = (1.0f - ALPHA_F) / (1.0f - p);
        a = beta;
        c = 1.0f - beta;
    }

    // ---- Fused affine on held registers, store ----
#pragma unroll
    for (int j = 0; j < 8; j++) {
        float4 r;
        r.x = fmaf(a, v[j].x, c);
        r.y = fmaf(a, v[j].y, c);
        r.z = fmaf(a, v[j].z, c);
        r.w = fmaf(a, v[j].w, c);
        o4[idx0 + j * BSTRIDE4] = r;
    }
}

extern "C" void kernel_launch(void* const* d_in, const int* in_sizes, int n_in,
                              void* d_out, int out_size) {
    const float* x   = (const float*)d_in[0];
    float*       out = (float*)d_out;
    // 256 h-rows x 16 w-chunks = 4096 blocks of 256 threads
    rescale_prob_mask_kernel<<<4096, 256>>>(x, out);
}